// round 7
// baseline (speedup 1.0000x reference)
#include <cuda_runtime.h>

#define Bn 256
#define Tn 2048
#define Dn 64
#define LBn 2
#define DBn 32
#define Gn 96
#define Ln 2
#define CH 16     // steps per chunk
#define RD 2      // ring depth in chunks (per-slot named barriers)

__device__ float g_dts[Bn * LBn * Tn];
__device__ int   g_cnt[Bn * LBn];

typedef unsigned long long u64;

__device__ __forceinline__ u64 ffma2(u64 a, u64 b, u64 c) {
    u64 d; asm("fma.rn.f32x2 %0,%1,%2,%3;" : "=l"(d) : "l"(a), "l"(b), "l"(c)); return d;
}
__device__ __forceinline__ u64 fadd2(u64 a, u64 b) {
    u64 d; asm("add.rn.f32x2 %0,%1,%2;" : "=l"(d) : "l"(a), "l"(b)); return d;
}
__device__ __forceinline__ float tanha(float x) {
    float y; asm("tanh.approx.f32 %0,%1;" : "=f"(y) : "f"(x)); return y;
}

__device__ __forceinline__ void bar_sync(int id) {
    asm volatile("bar.sync %0, 64;" :: "r"(id) : "memory");
}
__device__ __forceinline__ void bar_arrive(int id) {
    asm volatile("bar.arrive %0, 64;" :: "r"(id) : "memory");
}
__device__ __forceinline__ void membar_cta() {
    asm volatile("membar.cta;" ::: "memory");
}
__device__ __forceinline__ void cbar() { asm volatile("" ::: "memory"); }

// named barrier ids (count=64: one producer warp + one consumer warp)
#define B_R1 1   // +slot: W0 -> W2  (sH1 ready)
#define B_S1 3   // +slot: W2 -> W0  (sH1 slot free)
#define B_R2 5   // +slot: W2 -> W1  (sGX2 ready)
#define B_R3 7   // +slot: W1 -> W2  (sH2 ready; also implies sGX2 slot free)
#define B_S2 9   // +slot: W2 -> W1  (sH2 slot free)

union F2 { float2 f; u64 u; };
__device__ __forceinline__ u64 pack2(float a, float b) { F2 t; t.f = make_float2(a, b); return t.u; }
__device__ __forceinline__ float hsum(u64 a) { F2 t; t.u = a; return t.f.x + t.f.y; }

// dot of 32 floats (16 f32x2 pairs) with scalar init folded into accumulator
__device__ __forceinline__ float dot32i(const u64* w, const u64* hp, float init) {
    u64 a0 = pack2(init, 0.f), a1 = 0ull, a2 = 0ull, a3 = 0ull;
#pragma unroll
    for (int k = 0; k < 16; k += 4) {
        a0 = ffma2(w[k],     hp[k],     a0);
        a1 = ffma2(w[k + 1], hp[k + 1], a1);
        a2 = ffma2(w[k + 2], hp[k + 2], a2);
        a3 = ffma2(w[k + 3], hp[k + 3], a3);
    }
    return hsum(fadd2(fadd2(a0, a1), fadd2(a2, a3)));
}
__device__ __forceinline__ void loadrow(u64* w, const float* p, float s) {
#pragma unroll
    for (int k = 0; k < 16; k++) w[k] = pack2(p[2 * k] * s, p[2 * k + 1] * s);
}
__device__ __forceinline__ void loadhp(u64* hp, const float* row) {
    const ulonglong2* hv = (const ulonglong2*)row;
#pragma unroll
    for (int k = 0; k < 8; k++) { ulonglong2 v = hv[k]; hp[2 * k] = v.x; hp[2 * k + 1] = v.y; }
}

// ---------------------------------------------------------------------------
// Prep: stable compaction of dtime per (row, band) via block prefix scan.
// ---------------------------------------------------------------------------
__global__ void prep_kernel(const int* __restrict__ band_ids,
                            const float* __restrict__ dtime) {
    const int b = blockIdx.x;
    const int tid = threadIdx.x;
    __shared__ int s_scan[256];

    int loc[8]; int cnt = 0;
    const int base = b * Tn + tid * 8;
#pragma unroll
    for (int k = 0; k < 8; k++) { loc[k] = band_ids[base + k]; cnt += loc[k]; }
    s_scan[tid] = cnt;
    __syncthreads();
    for (int off = 1; off < 256; off <<= 1) {
        int v = s_scan[tid];
        int w = (tid >= off) ? s_scan[tid - off] : 0;
        __syncthreads();
        s_scan[tid] = v + w;
        __syncthreads();
    }
    const int total = s_scan[255];
    int ones_before = s_scan[tid] - cnt;
#pragma unroll
    for (int k = 0; k < 8; k++) {
        int t = tid * 8 + k;
        int bid = loc[k];
        int pos = bid ? ones_before : (t - ones_before);
        g_dts[(b * LBn + bid) * Tn + pos] = dtime[b * Tn + t];
        ones_before += bid;
    }
    if (tid == 0) {
        g_cnt[b * LBn + 1] = total;
        g_cnt[b * LBn + 0] = Tn - total;
    }
}

// ---------------------------------------------------------------------------
// Main: one block (3 warps) per chain, layer-pipelined, named-barrier sync.
// Gates via MUFU.TANH: sigmoid(x) = 0.5*tanh(x/2)+0.5, halves pre-folded
// into weights/biases. gh-dot accumulators initialized with gx+bias.
// ---------------------------------------------------------------------------
__global__ void __launch_bounds__(96, 4)
rnn_kernel(const float* __restrict__ zlast,
           const float* __restrict__ projW, const float* __restrict__ projB,
           const float* __restrict__ Wih,   const float* __restrict__ Whh,
           const float* __restrict__ bih,   const float* __restrict__ bhh,
           const float* __restrict__ mW1,   const float* __restrict__ mb1,
           const float* __restrict__ mW2,   const float* __restrict__ mb2,
           float* __restrict__ out) {
    const int kb = blockIdx.x & 1;
    const int b  = blockIdx.x >> 1;
    const int g  = threadIdx.x;
    const int lane = g & 31;
    const int warp = g >> 5;
    const int cid = b * LBn + kb;

    __shared__ __align__(16) float sDT[Tn];
    __shared__ __align__(16) float sH1[RD][CH][32];
    __shared__ __align__(16) float sGX2[RD][CH][96];
    __shared__ __align__(16) float sH2[RD][CH][32];
    __shared__ __align__(16) u64   sMW1p[16 * 32];
    __shared__ float sBase[32], sW[32], sZ[64];

    for (int i = g; i < Tn; i += 96) sDT[i] = g_dts[cid * Tn + i];
    if (g < 64) sZ[g] = zlast[b * Dn + g];
    for (int idx = g; idx < 16 * 32; idx += 96) {
        int k = idx >> 5, d = idx & 31;
        sMW1p[idx] = pack2(mW1[kb * 1024 + (2 * k) * 32 + d],
                           mW1[kb * 1024 + (2 * k + 1) * 32 + d]);
    }
    __syncthreads();

    const int n = g_cnt[cid];
    const int nch = (n + CH - 1) / CH;
    float* outp = out + (size_t)(kb * Bn + b) * Tn;
    const int l1 = (kb * Ln + 0) * Gn;
    const int l2 = (kb * Ln + 1) * Gn;

    if (warp == 0) {
        // -------- layer-1 recurrence --------
        u64 wr[16], wz[16], wn[16];
        loadrow(wr, &Whh[(l1 + lane) * DBn], 0.5f);
        loadrow(wz, &Whh[(l1 + lane + 32) * DBn], 0.5f);
        loadrow(wn, &Whh[(l1 + lane + 64) * DBn], 1.0f);
        const float bhn = bhh[l1 + lane + 64];   // full scale, r-multiplied

        float base = projB[kb * DBn + lane];
        float w = projW[(kb * (Dn + 1) + Dn) * DBn + lane];
#pragma unroll 8
        for (int i = 0; i < 64; i++) base += sZ[i] * projW[(kb * (Dn + 1) + i) * DBn + lane];
        sBase[lane] = base; sW[lane] = w;
        __syncwarp();

        // collapse layer-1 input gates: gx(t) = gb + dt*gw (pre-scaled, bhh folded for r,z)
        float gbr, gbz, gbn, gwr, gwz, gwn;
        {
            float ar = bih[l1 + lane], cr = 0.f;
            float az = bih[l1 + lane + 32], cz = 0.f;
            float an = bih[l1 + lane + 64], cn = 0.f;
#pragma unroll 8
            for (int d = 0; d < 32; d++) {
                float wv = Wih[(l1 + lane) * DBn + d];
                ar += wv * sBase[d]; cr += wv * sW[d];
                wv = Wih[(l1 + lane + 32) * DBn + d];
                az += wv * sBase[d]; cz += wv * sW[d];
                wv = Wih[(l1 + lane + 64) * DBn + d];
                an += wv * sBase[d]; cn += wv * sW[d];
            }
            gbr = 0.5f * (ar + bhh[l1 + lane]);      gwr = 0.5f * cr;
            gbz = 0.5f * (az + bhh[l1 + lane + 32]); gwz = 0.5f * cz;
            gbn = an;                                 gwn = cn;
        }

        float h1s = 0.f;
        u64 hp[16];
#pragma unroll
        for (int k = 0; k < 16; k++) hp[k] = 0ull;

        for (int c = 0; c < nch; c++) {
            const int slot = c & 1;
            if (c >= RD) bar_sync(B_S1 + slot);       // wait: W2 freed this slot
#pragma unroll
            for (int i = 0; i < CH; i++) {
                const float dt = sDT[c * CH + i];
                float sr  = dot32i(wr, hp, fmaf(dt, gwr, gbr));  // 0.5*(gx+gh)
                float sz  = dot32i(wz, hp, fmaf(dt, gwz, gbz));
                float ghn = dot32i(wn, hp, bhn);
                float gxn = fmaf(dt, gwn, gbn);
                float r  = fmaf(0.5f, tanha(sr), 0.5f);
                float z  = fmaf(0.5f, tanha(sz), 0.5f);
                float nn = tanha(fmaf(r, ghn, gxn));
                h1s = fmaf(z, h1s - nn, nn);
                sH1[slot][i][lane] = h1s;
                cbar();                                // warp-synchronous STS->LDS
                loadhp(hp, sH1[slot][i]);
            }
            membar_cta();
            bar_arrive(B_R1 + slot);                  // signal: sH1 chunk ready
        }
    } else if (warp == 1) {
        // -------- layer-2 recurrence --------
        u64 wr[16], wz[16], wn[16];
        loadrow(wr, &Whh[(l2 + lane) * DBn], 0.5f);
        loadrow(wz, &Whh[(l2 + lane + 32) * DBn], 0.5f);
        loadrow(wn, &Whh[(l2 + lane + 64) * DBn], 1.0f);
        const float bhn = bhh[l2 + lane + 64];
        // bhh2 r,z halves are folded into sGX2 by W2.

        float h2s = 0.f;
        u64 hp[16];
#pragma unroll
        for (int k = 0; k < 16; k++) hp[k] = 0ull;

        for (int c = 0; c < nch; c++) {
            const int slot = c & 1;
            bar_sync(B_R2 + slot);                    // wait: gx2 chunk ready
            if (c >= RD) bar_sync(B_S2 + slot);       // wait: W2 done with old sH2 slot
#pragma unroll
            for (int i = 0; i < CH; i++) {
                float gxr = sGX2[slot][i][lane];           // 0.5*(gx+bhh) folded
                float gxz = sGX2[slot][i][lane + 32];
                float gxn = sGX2[slot][i][lane + 64];      // full scale
                float sr  = dot32i(wr, hp, gxr);
                float sz  = dot32i(wz, hp, gxz);
                float ghn = dot32i(wn, hp, bhn);
                float r  = fmaf(0.5f, tanha(sr), 0.5f);
                float z  = fmaf(0.5f, tanha(sz), 0.5f);
                float nn = tanha(fmaf(r, ghn, gxn));
                h2s = fmaf(z, h2s - nn, nn);
                sH2[slot][i][lane] = h2s;
                cbar();
                loadhp(hp, sH2[slot][i]);
            }
            membar_cta();
            bar_arrive(B_R3 + slot);                  // signal: sH2 chunk ready (+ gx2 slot free)
        }
    } else {
        // -------- feedforward: gx2 producer + MLP consumer + tail --------
        u64 wr[16], wz[16], wn[16];
        loadrow(wr, &Wih[(l2 + lane) * DBn], 0.5f);
        loadrow(wz, &Wih[(l2 + lane + 32) * DBn], 0.5f);
        loadrow(wn, &Wih[(l2 + lane + 64) * DBn], 1.0f);
        // fold bih2 (and bhh2 for r,z) here, pre-scaled
        const float bir = 0.5f * (bih[l2 + lane] + bhh[l2 + lane]);
        const float biz = 0.5f * (bih[l2 + lane + 32] + bhh[l2 + lane + 32]);
        const float bin = bih[l2 + lane + 64];
        const float mb1v = mb1[kb * DBn + lane];
        const float mw2v = mW2[kb * DBn + lane];
        const float mb2v = mb2[kb];
        float yl = 0.f;

        for (int c = 0; c < nch; c++) {
            const int slot = c & 1;
            bar_sync(B_R1 + slot);                    // wait: sH1 chunk ready
#pragma unroll
            for (int i = 0; i < CH; i++) {
                u64 hp[16];
                loadhp(hp, sH1[slot][i]);
                sGX2[slot][i][lane]      = dot32i(wr, hp, bir);
                sGX2[slot][i][lane + 32] = dot32i(wz, hp, biz);
                sGX2[slot][i][lane + 64] = dot32i(wn, hp, bin);
            }
            membar_cta();
            bar_arrive(B_R2 + slot);                  // signal: gx2 ready
            bar_arrive(B_S1 + slot);                  // signal: sH1 slot free

            if (c >= 1) {
                const int cc = c - 1;
                const int ss = cc & 1;
                bar_sync(B_R3 + ss);                  // wait: sH2 chunk ready
#pragma unroll
                for (int i = 0; i < CH; i++) {
                    const int t = cc * CH + i;
                    u64 hp[16];
                    loadhp(hp, sH2[ss][i]);
                    u64 a0 = 0ull, a1 = 0ull;
#pragma unroll
                    for (int k = 0; k < 16; k += 2) {
                        a0 = ffma2(sMW1p[k * 32 + lane], hp[k], a0);
                        a1 = ffma2(sMW1p[(k + 1) * 32 + lane], hp[k + 1], a1);
                    }
                    float m = fmaxf(hsum(fadd2(a0, a1)) + mb1v, 0.f);
                    float y = m * mw2v;
#pragma unroll
                    for (int off = 16; off > 0; off >>= 1) y += __shfl_xor_sync(0xffffffffu, y, off);
                    y += mb2v;
                    if (lane == 0 && t < n) outp[t] = y;
                    if (t == n - 1) yl = y;
                }
                bar_arrive(B_S2 + ss);                // signal: sH2 slot free
            }
        }
        if (nch >= 1) {
            const int cc = nch - 1;
            const int ss = cc & 1;
            bar_sync(B_R3 + ss);
#pragma unroll
            for (int i = 0; i < CH; i++) {
                const int t = cc * CH + i;
                u64 hp[16];
                loadhp(hp, sH2[ss][i]);
                u64 a0 = 0ull, a1 = 0ull;
#pragma unroll
                for (int k = 0; k < 16; k += 2) {
                    a0 = ffma2(sMW1p[k * 32 + lane], hp[k], a0);
                    a1 = ffma2(sMW1p[(k + 1) * 32 + lane], hp[k + 1], a1);
                }
                float m = fmaxf(hsum(fadd2(a0, a1)) + mb1v, 0.f);
                float y = m * mw2v;
#pragma unroll
                for (int off = 16; off > 0; off >>= 1) y += __shfl_xor_sync(0xffffffffu, y, off);
                y += mb2v;
                if (lane == 0 && t < n) outp[t] = y;
                if (t == n - 1) yl = y;
            }
            bar_arrive(B_S2 + ss);
        }
        if (n == 0) {
            float m = fmaxf(mb1v, 0.f);
            float y = m * mw2v;
#pragma unroll
            for (int off = 16; off > 0; off >>= 1) y += __shfl_xor_sync(0xffffffffu, y, off);
            yl = y + mb2v;
        }
        for (int t = n + lane; t < Tn; t += 32) outp[t] = yl;
    }
}

extern "C" void kernel_launch(void* const* d_in, const int* in_sizes, int n_in,
                              void* d_out, int out_size) {
    const int*   band_ids = (const int*)  d_in[0];
    const float* dtime    = (const float*)d_in[1];
    const float* zlast    = (const float*)d_in[2];
    const float* projW    = (const float*)d_in[3];
    const float* projB    = (const float*)d_in[4];
    const float* Wih      = (const float*)d_in[5];
    const float* Whh      = (const float*)d_in[6];
    const float* bihp     = (const float*)d_in[7];
    const float* bhhp     = (const float*)d_in[8];
    const float* mW1      = (const float*)d_in[9];
    const float* mb1      = (const float*)d_in[10];
    const float* mW2      = (const float*)d_in[11];
    const float* mb2      = (const float*)d_in[12];

    prep_kernel<<<Bn, 256>>>(band_ids, dtime);
    rnn_kernel<<<Bn * LBn, 96>>>(zlast, projW, projB, Wih, Whh, bihp, bhhp,
                                 mW1, mb1, mW2, mb2, (float*)d_out);
}

// round 9
// speedup vs baseline: 1.4648x; 1.4648x over previous
#include <cuda_runtime.h>

#define Bn 256
#define Tn 2048
#define Dn 64
#define LBn 2
#define DBn 32
#define Gn 96
#define Ln 2
#define CH 8      // steps per chunk
#define RD 2      // ring depth in chunks

__device__ float g_dts[Bn * LBn * Tn];
__device__ int   g_cnt[Bn * LBn];

typedef unsigned long long u64;

__device__ __forceinline__ u64 ffma2(u64 a, u64 b, u64 c) {
    u64 d; asm("fma.rn.f32x2 %0,%1,%2,%3;" : "=l"(d) : "l"(a), "l"(b), "l"(c)); return d;
}
__device__ __forceinline__ u64 fadd2(u64 a, u64 b) {
    u64 d; asm("add.rn.f32x2 %0,%1,%2;" : "=l"(d) : "l"(a), "l"(b)); return d;
}
__device__ __forceinline__ float tanha(float x) {
    float y; asm("tanh.approx.f32 %0,%1;" : "=f"(y) : "f"(x)); return y;
}
__device__ __forceinline__ void bar_sync(int id) {
    asm volatile("bar.sync %0, 64;" :: "r"(id) : "memory");
}
__device__ __forceinline__ void bar_arrive(int id) {
    asm volatile("bar.arrive %0, 64;" :: "r"(id) : "memory");
}
__device__ __forceinline__ void membar_cta() {
    asm volatile("membar.cta;" ::: "memory");
}
__device__ __forceinline__ void cbar() { asm volatile("" ::: "memory"); }

// named barrier ids: ring handshake between the 2 warps (count = 64)
#define B_RDY 1   // +slot: W0 -> W1  (gx2 chunk ready)
#define B_FRE 3   // +slot: W1 -> W0  (gx2 slot free)

union F2 { float2 f; u64 u; };
__device__ __forceinline__ u64 pack2(float a, float b) { F2 t; t.f = make_float2(a, b); return t.u; }
__device__ __forceinline__ float hsum(u64 a) { F2 t; t.u = a; return t.f.x + t.f.y; }

// dot of 32 floats (16 f32x2 pairs), scalar init folded into accumulator
__device__ __forceinline__ float dot32i(const u64* w, const u64* hp, float init) {
    u64 a0 = pack2(init, 0.f), a1 = 0ull, a2 = 0ull, a3 = 0ull;
#pragma unroll
    for (int k = 0; k < 16; k += 4) {
        a0 = ffma2(w[k],     hp[k],     a0);
        a1 = ffma2(w[k + 1], hp[k + 1], a1);
        a2 = ffma2(w[k + 2], hp[k + 2], a2);
        a3 = ffma2(w[k + 3], hp[k + 3], a3);
    }
    return hsum(fadd2(fadd2(a0, a1), fadd2(a2, a3)));
}
__device__ __forceinline__ void loadrow(u64* w, const float* p, float s) {
#pragma unroll
    for (int k = 0; k < 16; k++) w[k] = pack2(p[2 * k] * s, p[2 * k + 1] * s);
}
__device__ __forceinline__ void loadhp(u64* hp, const float* row) {
    const ulonglong2* hv = (const ulonglong2*)row;
#pragma unroll
    for (int k = 0; k < 8; k++) { ulonglong2 v = hv[k]; hp[2 * k] = v.x; hp[2 * k + 1] = v.y; }
}

// ---------------------------------------------------------------------------
// Prep: stable compaction of dtime per (row, band) via block prefix scan.
// ---------------------------------------------------------------------------
__global__ void prep_kernel(const int* __restrict__ band_ids,
                            const float* __restrict__ dtime) {
    const int b = blockIdx.x;
    const int tid = threadIdx.x;
    __shared__ int s_scan[256];

    int loc[8]; int cnt = 0;
    const int base = b * Tn + tid * 8;
#pragma unroll
    for (int k = 0; k < 8; k++) { loc[k] = band_ids[base + k]; cnt += loc[k]; }
    s_scan[tid] = cnt;
    __syncthreads();
    for (int off = 1; off < 256; off <<= 1) {
        int v = s_scan[tid];
        int w = (tid >= off) ? s_scan[tid - off] : 0;
        __syncthreads();
        s_scan[tid] = v + w;
        __syncthreads();
    }
    const int total = s_scan[255];
    int ones_before = s_scan[tid] - cnt;
#pragma unroll
    for (int k = 0; k < 8; k++) {
        int t = tid * 8 + k;
        int bid = loc[k];
        int pos = bid ? ones_before : (t - ones_before);
        g_dts[(b * LBn + bid) * Tn + pos] = dtime[b * Tn + t];
        ones_before += bid;
    }
    if (tid == 0) {
        g_cnt[b * LBn + 1] = total;
        g_cnt[b * LBn + 0] = Tn - total;
    }
}

// ---------------------------------------------------------------------------
// Main: one block (2 warps, 64 threads) per chain.
//   W0: layer-1 recurrence + gx2 = Wih2 @ h1  -> sGX2 ring
//   W1: layer-2 recurrence + MLP head + output + tail fill
// 256-reg budget per thread (launch_bounds 64,4) -> no spills.
// sigmoid(x) = 0.5*tanh(x/2)+0.5 with halves pre-folded into weights/biases.
// ---------------------------------------------------------------------------
__global__ void __launch_bounds__(64, 4)
rnn_kernel(const float* __restrict__ zlast,
           const float* __restrict__ projW, const float* __restrict__ projB,
           const float* __restrict__ Wih,   const float* __restrict__ Whh,
           const float* __restrict__ bih,   const float* __restrict__ bhh,
           const float* __restrict__ mW1,   const float* __restrict__ mb1,
           const float* __restrict__ mW2,   const float* __restrict__ mb2,
           float* __restrict__ out) {
    const int kb = blockIdx.x & 1;
    const int b  = blockIdx.x >> 1;
    const int g  = threadIdx.x;
    const int lane = g & 31;
    const int warp = g >> 5;
    const int cid = b * LBn + kb;

    __shared__ __align__(16) float sDT[Tn];
    __shared__ __align__(16) float sGX2[RD][CH][96];
    __shared__ __align__(16) float sH1b[32];   // W0-private h1 broadcast buffer
    __shared__ __align__(16) float sH2b[32];   // W1-private h2 broadcast buffer
    __shared__ __align__(16) u64   sMW1p[16 * 32];
    __shared__ float sBase[32], sW[32], sZ[64];

    for (int i = g; i < Tn; i += 64) sDT[i] = g_dts[cid * Tn + i];
    if (g < 64) sZ[g] = zlast[b * Dn + g];
    for (int idx = g; idx < 16 * 32; idx += 64) {
        int k = idx >> 5, d = idx & 31;
        sMW1p[idx] = pack2(mW1[kb * 1024 + (2 * k) * 32 + d],
                           mW1[kb * 1024 + (2 * k + 1) * 32 + d]);
    }
    if (g < 32) { sH1b[g] = 0.f; sH2b[g] = 0.f; }
    __syncthreads();

    const int n = g_cnt[cid];
    const int nch = (n + CH - 1) / CH;
    float* outp = out + (size_t)(kb * Bn + b) * Tn;
    const int l1 = (kb * Ln + 0) * Gn;
    const int l2 = (kb * Ln + 1) * Gn;

    if (warp == 0) {
        // ---- layer-1 recurrence + gx2 production ----
        u64 wr[16], wz[16], wn[16];        // Whh layer1 (r,z half-scaled)
        loadrow(wr, &Whh[(l1 + lane) * DBn], 0.5f);
        loadrow(wz, &Whh[(l1 + lane + 32) * DBn], 0.5f);
        loadrow(wn, &Whh[(l1 + lane + 64) * DBn], 1.0f);
        u64 vr[16], vz[16], vn[16];        // Wih layer2 (r,z half-scaled)
        loadrow(vr, &Wih[(l2 + lane) * DBn], 0.5f);
        loadrow(vz, &Wih[(l2 + lane + 32) * DBn], 0.5f);
        loadrow(vn, &Wih[(l2 + lane + 64) * DBn], 1.0f);
        const float bhn1 = bhh[l1 + lane + 64];
        // layer-2 input-gate biases (bih2 + bhh2 for r,z folded, half-scaled)
        const float bir2 = 0.5f * (bih[l2 + lane] + bhh[l2 + lane]);
        const float biz2 = 0.5f * (bih[l2 + lane + 32] + bhh[l2 + lane + 32]);
        const float bin2 = bih[l2 + lane + 64];

        // input projection: x_t = base + dt*w
        float base = projB[kb * DBn + lane];
        float w = projW[(kb * (Dn + 1) + Dn) * DBn + lane];
#pragma unroll 8
        for (int i = 0; i < 64; i++) base += sZ[i] * projW[(kb * (Dn + 1) + i) * DBn + lane];
        sBase[lane] = base; sW[lane] = w;
        __syncwarp();

        // collapse layer-1 input gates: gx(t) = gb + dt*gw
        float gbr, gbz, gbn, gwr, gwz, gwn;
        {
            float ar = bih[l1 + lane], cr = 0.f;
            float az = bih[l1 + lane + 32], cz = 0.f;
            float an = bih[l1 + lane + 64], cn = 0.f;
#pragma unroll 8
            for (int d = 0; d < 32; d++) {
                float wv = Wih[(l1 + lane) * DBn + d];
                ar += wv * sBase[d]; cr += wv * sW[d];
                wv = Wih[(l1 + lane + 32) * DBn + d];
                az += wv * sBase[d]; cz += wv * sW[d];
                wv = Wih[(l1 + lane + 64) * DBn + d];
                an += wv * sBase[d]; cn += wv * sW[d];
            }
            gbr = 0.5f * (ar + bhh[l1 + lane]);      gwr = 0.5f * cr;
            gbz = 0.5f * (az + bhh[l1 + lane + 32]); gwz = 0.5f * cz;
            gbn = an;                                 gwn = cn;
        }

        float h1s = 0.f;
        u64 hp[16];
#pragma unroll
        for (int k = 0; k < 16; k++) hp[k] = 0ull;

        for (int c = 0; c < nch; c++) {
            const int slot = c & 1;
            if (c >= RD) bar_sync(B_FRE + slot);       // wait: W1 freed slot
#pragma unroll
            for (int i = 0; i < CH; i++) {
                const float dt = sDT[c * CH + i];
                // layer-1 recurrence (critical chain)
                float sr  = dot32i(wr, hp, fmaf(dt, gwr, gbr));
                float sz  = dot32i(wz, hp, fmaf(dt, gwz, gbz));
                float ghn = dot32i(wn, hp, bhn1);
                float gxn = fmaf(dt, gwn, gbn);
                float r  = fmaf(0.5f, tanha(sr), 0.5f);
                float z  = fmaf(0.5f, tanha(sz), 0.5f);
                float nn = tanha(fmaf(r, ghn, gxn));
                h1s = fmaf(z, h1s - nn, nn);
                sH1b[lane] = h1s;
                cbar();                                 // warp-synchronous STS->LDS
                loadhp(hp, sH1b);
                // gx2 for layer 2 (feedforward, off-chain)
                sGX2[slot][i][lane]      = dot32i(vr, hp, bir2);
                sGX2[slot][i][lane + 32] = dot32i(vz, hp, biz2);
                sGX2[slot][i][lane + 64] = dot32i(vn, hp, bin2);
            }
            membar_cta();
            bar_arrive(B_RDY + slot);                  // signal: gx2 chunk ready
        }
    } else {
        // ---- layer-2 recurrence + MLP head + output ----
        u64 wr[16], wz[16], wn[16];        // Whh layer2 (r,z half-scaled)
        loadrow(wr, &Whh[(l2 + lane) * DBn], 0.5f);
        loadrow(wz, &Whh[(l2 + lane + 32) * DBn], 0.5f);
        loadrow(wn, &Whh[(l2 + lane + 64) * DBn], 1.0f);
        const float bhn2 = bhh[l2 + lane + 64];
        const float mb1v = mb1[kb * DBn + lane];
        const float mw2v = mW2[kb * DBn + lane];
        const float mb2v = mb2[kb];
        float yl = 0.f;

        float h2s = 0.f;
        u64 hp[16];
#pragma unroll
        for (int k = 0; k < 16; k++) hp[k] = 0ull;

        for (int c = 0; c < nch; c++) {
            const int slot = c & 1;
            bar_sync(B_RDY + slot);                    // wait: gx2 chunk ready
#pragma unroll
            for (int i = 0; i < CH; i++) {
                const int t = c * CH + i;
                float gxr = sGX2[slot][i][lane];
                float gxz = sGX2[slot][i][lane + 32];
                float gxn = sGX2[slot][i][lane + 64];
                float sr  = dot32i(wr, hp, gxr);
                float sz  = dot32i(wz, hp, gxz);
                float ghn = dot32i(wn, hp, bhn2);
                float r  = fmaf(0.5f, tanha(sr), 0.5f);
                float z  = fmaf(0.5f, tanha(sz), 0.5f);
                float nn = tanha(fmaf(r, ghn, gxn));
                h2s = fmaf(z, h2s - nn, nn);
                sH2b[lane] = h2s;
                cbar();
                loadhp(hp, sH2b);
                // MLP head (off-chain ILP)
                u64 a0 = 0ull, a1 = 0ull;
#pragma unroll
                for (int k = 0; k < 16; k += 2) {
                    a0 = ffma2(sMW1p[k * 32 + lane], hp[k], a0);
                    a1 = ffma2(sMW1p[(k + 1) * 32 + lane], hp[k + 1], a1);
                }
                float m = fmaxf(hsum(fadd2(a0, a1)) + mb1v, 0.f);
                float y = m * mw2v;
#pragma unroll
                for (int off = 16; off > 0; off >>= 1) y += __shfl_xor_sync(0xffffffffu, y, off);
                y += mb2v;
                if (lane == 0 && t < n) outp[t] = y;
                if (t == n - 1) yl = y;
            }
            bar_arrive(B_FRE + slot);                  // signal: gx2 slot free
        }
        if (n == 0) {
            float m = fmaxf(mb1v, 0.f);
            float y = m * mw2v;
#pragma unroll
            for (int off = 16; off > 0; off >>= 1) y += __shfl_xor_sync(0xffffffffu, y, off);
            yl = y + mb2v;
        }
        for (int t = n + lane; t < Tn; t += 32) outp[t] = yl;
    }
}

extern "C" void kernel_launch(void* const* d_in, const int* in_sizes, int n_in,
                              void* d_out, int out_size) {
    const int*   band_ids = (const int*)  d_in[0];
    const float* dtime    = (const float*)d_in[1];
    const float* zlast    = (const float*)d_in[2];
    const float* projW    = (const float*)d_in[3];
    const float* projB    = (const float*)d_in[4];
    const float* Wih      = (const float*)d_in[5];
    const float* Whh      = (const float*)d_in[6];
    const float* bihp     = (const float*)d_in[7];
    const float* bhhp     = (const float*)d_in[8];
    const float* mW1      = (const float*)d_in[9];
    const float* mb1      = (const float*)d_in[10];
    const float* mW2      = (const float*)d_in[11];
    const float* mb2      = (const float*)d_in[12];

    prep_kernel<<<Bn, 256>>>(band_ids, dtime);
    rnn_kernel<<<Bn * LBn, 64>>>(zlast, projW, projB, Wih, Whh, bihp, bhhp,
                                 mW1, mb1, mW2, mb2, (float*)d_out);
}

// round 10
// speedup vs baseline: 1.6181x; 1.1047x over previous
#include <cuda_runtime.h>

#define Bn 256
#define Tn 2048
#define Dn 64
#define LBn 2
#define DBn 32
#define Gn 96
#define Ln 2
#define CH 8      // steps per chunk
#define RD 2      // ring depth in chunks
#define CPB 4     // chains per block

__device__ float g_dts[Bn * LBn * Tn + 16];
__device__ int   g_cnt[Bn * LBn];

typedef unsigned long long u64;

__device__ __forceinline__ u64 ffma2(u64 a, u64 b, u64 c) {
    u64 d; asm("fma.rn.f32x2 %0,%1,%2,%3;" : "=l"(d) : "l"(a), "l"(b), "l"(c)); return d;
}
__device__ __forceinline__ u64 fadd2(u64 a, u64 b) {
    u64 d; asm("add.rn.f32x2 %0,%1,%2;" : "=l"(d) : "l"(a), "l"(b)); return d;
}
__device__ __forceinline__ float tanha(float x) {
    float y; asm("tanh.approx.f32 %0,%1;" : "=f"(y) : "f"(x)); return y;
}
__device__ __forceinline__ void bar_sync(int id) {
    asm volatile("bar.sync %0, 64;" :: "r"(id) : "memory");
}
__device__ __forceinline__ void bar_arrive(int id) {
    asm volatile("bar.arrive %0, 64;" :: "r"(id) : "memory");
}
__device__ __forceinline__ void membar_cta() {
    asm volatile("membar.cta;" ::: "memory");
}
__device__ __forceinline__ void cbar() { asm volatile("" ::: "memory"); }

union F2 { float2 f; u64 u; };
__device__ __forceinline__ u64 pack2(float a, float b) { F2 t; t.f = make_float2(a, b); return t.u; }
__device__ __forceinline__ float hsum(u64 a) { F2 t; t.u = a; return t.f.x + t.f.y; }

// dot of 32 floats (16 f32x2 pairs), scalar init folded into accumulator
__device__ __forceinline__ float dot32i(const u64* w, const u64* hp, float init) {
    u64 a0 = pack2(init, 0.f), a1 = 0ull, a2 = 0ull, a3 = 0ull;
#pragma unroll
    for (int k = 0; k < 16; k += 4) {
        a0 = ffma2(w[k],     hp[k],     a0);
        a1 = ffma2(w[k + 1], hp[k + 1], a1);
        a2 = ffma2(w[k + 2], hp[k + 2], a2);
        a3 = ffma2(w[k + 3], hp[k + 3], a3);
    }
    return hsum(fadd2(fadd2(a0, a1), fadd2(a2, a3)));
}
// dot with weights in shared memory, layout [k][32 lanes]
__device__ __forceinline__ float dot32s(const u64* ws, int lane, const u64* hp, float init) {
    u64 a0 = pack2(init, 0.f), a1 = 0ull, a2 = 0ull, a3 = 0ull;
#pragma unroll
    for (int k = 0; k < 16; k += 4) {
        a0 = ffma2(ws[(k    ) * 32 + lane], hp[k],     a0);
        a1 = ffma2(ws[(k + 1) * 32 + lane], hp[k + 1], a1);
        a2 = ffma2(ws[(k + 2) * 32 + lane], hp[k + 2], a2);
        a3 = ffma2(ws[(k + 3) * 32 + lane], hp[k + 3], a3);
    }
    return hsum(fadd2(fadd2(a0, a1), fadd2(a2, a3)));
}
__device__ __forceinline__ void loadrow(u64* w, const float* p, float s) {
#pragma unroll
    for (int k = 0; k < 16; k++) w[k] = pack2(p[2 * k] * s, p[2 * k + 1] * s);
}
__device__ __forceinline__ void loadhp(u64* hp, const float* row) {
    const ulonglong2* hv = (const ulonglong2*)row;
#pragma unroll
    for (int k = 0; k < 8; k++) { ulonglong2 v = hv[k]; hp[2 * k] = v.x; hp[2 * k + 1] = v.y; }
}

// ---------------------------------------------------------------------------
// Prep: stable compaction of dtime per (row, band) via block prefix scan.
// ---------------------------------------------------------------------------
__global__ void prep_kernel(const int* __restrict__ band_ids,
                            const float* __restrict__ dtime) {
    const int b = blockIdx.x;
    const int tid = threadIdx.x;
    __shared__ int s_scan[256];

    int loc[8]; int cnt = 0;
    const int base = b * Tn + tid * 8;
#pragma unroll
    for (int k = 0; k < 8; k++) { loc[k] = band_ids[base + k]; cnt += loc[k]; }
    s_scan[tid] = cnt;
    __syncthreads();
    for (int off = 1; off < 256; off <<= 1) {
        int v = s_scan[tid];
        int w = (tid >= off) ? s_scan[tid - off] : 0;
        __syncthreads();
        s_scan[tid] = v + w;
        __syncthreads();
    }
    const int total = s_scan[255];
    int ones_before = s_scan[tid] - cnt;
#pragma unroll
    for (int k = 0; k < 8; k++) {
        int t = tid * 8 + k;
        int bid = loc[k];
        int pos = bid ? ones_before : (t - ones_before);
        g_dts[(b * LBn + bid) * Tn + pos] = dtime[b * Tn + t];
        ones_before += bid;
    }
    if (tid == 0) {
        g_cnt[b * LBn + 1] = total;
        g_cnt[b * LBn + 0] = Tn - total;
    }
}

// ---------------------------------------------------------------------------
// Main: 4 chains per 256-thread block (8 warps).
//   chain = wid & 3  (spreads each role across all 4 SMSPs)
//   role  = wid >> 2:  0 = layer-1 recurrence + gx2 producer
//                      1 = layer-2 recurrence + MLP head + output
// Named barriers: chain c uses ids c*4 + {0,1} (RDY slot) and c*4 + {2,3} (FRE slot).
// ---------------------------------------------------------------------------
__global__ void __launch_bounds__(256, 1)
rnn_kernel(const float* __restrict__ zlast,
           const float* __restrict__ projW, const float* __restrict__ projB,
           const float* __restrict__ Wih,   const float* __restrict__ Whh,
           const float* __restrict__ bih,   const float* __restrict__ bhh,
           const float* __restrict__ mW1,   const float* __restrict__ mb1,
           const float* __restrict__ mW2,   const float* __restrict__ mb2,
           float* __restrict__ out) {
    const int tid  = threadIdx.x;
    const int lane = tid & 31;
    const int wid  = tid >> 5;
    const int chain = wid & 3;
    const int role  = wid >> 2;

    const int cid = blockIdx.x * CPB + chain;   // == b*LBn + kb
    const int kb  = cid & 1;
    const int b   = cid >> 1;

    __shared__ __align__(16) float sGX2[CPB][RD][CH][96];
    __shared__ __align__(16) u64   sMW1p[2][16 * 32];
    __shared__ __align__(16) u64   sWn2[2][16 * 32];   // Wih layer2 n-gate, [k][lane]
    __shared__ __align__(16) float sH1b[CPB][32];
    __shared__ __align__(16) float sH2b[CPB][32];
    __shared__ float sBase[CPB][32], sW[CPB][32], sZ[CPB][64];

    // cooperative init of per-kb shared tables
    for (int idx = tid; idx < 2 * 16 * 32; idx += 256) {
        int kbv = idx >> 9, r = idx & 511;
        int k = r >> 5, d = r & 31;
        sMW1p[kbv][r] = pack2(mW1[kbv * 1024 + (2 * k) * 32 + d],
                              mW1[kbv * 1024 + (2 * k + 1) * 32 + d]);
        int l2v = (kbv * Ln + 1) * Gn;
        sWn2[kbv][r] = pack2(Wih[(l2v + 64 + d) * DBn + 2 * k],
                             Wih[(l2v + 64 + d) * DBn + 2 * k + 1]);
    }
    // per-chain z and h init (role-0 warp of each chain)
    if (role == 0) {
        sZ[chain][lane]      = zlast[b * Dn + lane];
        sZ[chain][lane + 32] = zlast[b * Dn + lane + 32];
        sH1b[chain][lane] = 0.f;
        sH2b[chain][lane] = 0.f;
    }
    __syncthreads();

    const int n = g_cnt[cid];
    const int nch = (n + CH - 1) / CH;
    float* outp = out + (size_t)(kb * Bn + b) * Tn;
    const float* dts = g_dts + cid * Tn;
    const int l1 = (kb * Ln + 0) * Gn;
    const int l2 = (kb * Ln + 1) * Gn;
    const int bRDY = chain * 4;       // +slot
    const int bFRE = chain * 4 + 2;   // +slot

    if (role == 0) {
        // ---- layer-1 recurrence + gx2 production ----
        u64 wr[16], wz[16], wn[16];        // Whh layer1 (r,z half-scaled)
        loadrow(wr, &Whh[(l1 + lane) * DBn], 0.5f);
        loadrow(wz, &Whh[(l1 + lane + 32) * DBn], 0.5f);
        loadrow(wn, &Whh[(l1 + lane + 64) * DBn], 1.0f);
        u64 vr[16], vz[16];                // Wih layer2 r,z (half-scaled); n-gate in smem
        loadrow(vr, &Wih[(l2 + lane) * DBn], 0.5f);
        loadrow(vz, &Wih[(l2 + lane + 32) * DBn], 0.5f);
        const float bhn1 = bhh[l1 + lane + 64];
        const float bir2 = 0.5f * (bih[l2 + lane] + bhh[l2 + lane]);
        const float biz2 = 0.5f * (bih[l2 + lane + 32] + bhh[l2 + lane + 32]);
        const float bin2 = bih[l2 + lane + 64];

        // input projection: x_t = base + dt*w
        float base = projB[kb * DBn + lane];
        float w = projW[(kb * (Dn + 1) + Dn) * DBn + lane];
#pragma unroll 8
        for (int i = 0; i < 64; i++) base += sZ[chain][i] * projW[(kb * (Dn + 1) + i) * DBn + lane];
        sBase[chain][lane] = base; sW[chain][lane] = w;
        __syncwarp();

        // collapse layer-1 input gates: gx(t) = gb + dt*gw
        float gbr, gbz, gbn, gwr, gwz, gwn;
        {
            float ar = bih[l1 + lane], cr = 0.f;
            float az = bih[l1 + lane + 32], cz = 0.f;
            float an = bih[l1 + lane + 64], cn = 0.f;
#pragma unroll 8
            for (int d = 0; d < 32; d++) {
                float wv = Wih[(l1 + lane) * DBn + d];
                ar += wv * sBase[chain][d]; cr += wv * sW[chain][d];
                wv = Wih[(l1 + lane + 32) * DBn + d];
                az += wv * sBase[chain][d]; cz += wv * sW[chain][d];
                wv = Wih[(l1 + lane + 64) * DBn + d];
                an += wv * sBase[chain][d]; cn += wv * sW[chain][d];
            }
            gbr = 0.5f * (ar + bhh[l1 + lane]);      gwr = 0.5f * cr;
            gbz = 0.5f * (az + bhh[l1 + lane + 32]); gwz = 0.5f * cz;
            gbn = an;                                 gwn = cn;
        }

        float h1s = 0.f;
        u64 hp[16];
#pragma unroll
        for (int k = 0; k < 16; k++) hp[k] = 0ull;

        float dtb[CH];
#pragma unroll
        for (int i = 0; i < CH; i++) dtb[i] = dts[i];

        const u64* wns = sWn2[kb];

        for (int c = 0; c < nch; c++) {
            const int slot = c & 1;
            if (c >= RD) bar_sync(bFRE + slot);        // wait: W1 freed slot
            float dtn[CH];                              // prefetch next chunk's dt
#pragma unroll
            for (int i = 0; i < CH; i++) dtn[i] = dts[(c + 1) * CH + i];
#pragma unroll
            for (int i = 0; i < CH; i++) {
                const float dt = dtb[i];
                // layer-1 recurrence (critical chain)
                float sr  = dot32i(wr, hp, fmaf(dt, gwr, gbr));
                float sz  = dot32i(wz, hp, fmaf(dt, gwz, gbz));
                float ghn = dot32i(wn, hp, bhn1);
                float gxn = fmaf(dt, gwn, gbn);
                float r  = fmaf(0.5f, tanha(sr), 0.5f);
                float z  = fmaf(0.5f, tanha(sz), 0.5f);
                float nn = tanha(fmaf(r, ghn, gxn));
                h1s = fmaf(z, h1s - nn, nn);
                sH1b[chain][lane] = h1s;
                cbar();                                 // warp-synchronous STS->LDS
                loadhp(hp, sH1b[chain]);
                // gx2 for layer 2 (feedforward, off-chain)
                sGX2[chain][slot][i][lane]      = dot32i(vr, hp, bir2);
                sGX2[chain][slot][i][lane + 32] = dot32i(vz, hp, biz2);
                sGX2[chain][slot][i][lane + 64] = dot32s(wns, lane, hp, bin2);
            }
            membar_cta();
            bar_arrive(bRDY + slot);                   // signal: gx2 chunk ready
#pragma unroll
            for (int i = 0; i < CH; i++) dtb[i] = dtn[i];
        }
    } else {
        // ---- layer-2 recurrence + MLP head + output ----
        u64 wr[16], wz[16], wn[16];        // Whh layer2 (r,z half-scaled)
        loadrow(wr, &Whh[(l2 + lane) * DBn], 0.5f);
        loadrow(wz, &Whh[(l2 + lane + 32) * DBn], 0.5f);
        loadrow(wn, &Whh[(l2 + lane + 64) * DBn], 1.0f);
        const float bhn2 = bhh[l2 + lane + 64];
        const float mb1v = mb1[kb * DBn + lane];
        const float mw2v = mW2[kb * DBn + lane];
        const float mb2v = mb2[kb];
        const u64* mwp = sMW1p[kb];
        float yl = 0.f;

        float h2s = 0.f;
        u64 hp[16];
#pragma unroll
        for (int k = 0; k < 16; k++) hp[k] = 0ull;

        for (int c = 0; c < nch; c++) {
            const int slot = c & 1;
            bar_sync(bRDY + slot);                     // wait: gx2 chunk ready
#pragma unroll
            for (int i = 0; i < CH; i++) {
                const int t = c * CH + i;
                float gxr = sGX2[chain][slot][i][lane];
                float gxz = sGX2[chain][slot][i][lane + 32];
                float gxn = sGX2[chain][slot][i][lane + 64];
                float sr  = dot32i(wr, hp, gxr);
                float sz  = dot32i(wz, hp, gxz);
                float ghn = dot32i(wn, hp, bhn2);
                float r  = fmaf(0.5f, tanha(sr), 0.5f);
                float z  = fmaf(0.5f, tanha(sz), 0.5f);
                float nn = tanha(fmaf(r, ghn, gxn));
                h2s = fmaf(z, h2s - nn, nn);
                sH2b[chain][lane] = h2s;
                cbar();
                loadhp(hp, sH2b[chain]);
                // MLP head (off-chain ILP)
                u64 a0 = 0ull, a1 = 0ull;
#pragma unroll
                for (int k = 0; k < 16; k += 2) {
                    a0 = ffma2(mwp[k * 32 + lane], hp[k], a0);
                    a1 = ffma2(mwp[(k + 1) * 32 + lane], hp[k + 1], a1);
                }
                float m = fmaxf(hsum(fadd2(a0, a1)) + mb1v, 0.f);
                float y = m * mw2v;
#pragma unroll
                for (int off = 16; off > 0; off >>= 1) y += __shfl_xor_sync(0xffffffffu, y, off);
                y += mb2v;
                if (lane == 0 && t < n) outp[t] = y;
                if (t == n - 1) yl = y;
            }
            bar_arrive(bFRE + slot);                   // signal: gx2 slot free
        }
        if (n == 0) {
            float m = fmaxf(mb1v, 0.f);
            float y = m * mw2v;
#pragma unroll
            for (int off = 16; off > 0; off >>= 1) y += __shfl_xor_sync(0xffffffffu, y, off);
            yl = y + mb2v;
        }
        for (int t = n + lane; t < Tn; t += 32) outp[t] = yl;
    }
}

extern "C" void kernel_launch(void* const* d_in, const int* in_sizes, int n_in,
                              void* d_out, int out_size) {
    const int*   band_ids = (const int*)  d_in[0];
    const float* dtime    = (const float*)d_in[1];
    const float* zlast    = (const float*)d_in[2];
    const float* projW    = (const float*)d_in[3];
    const float* projB    = (const float*)d_in[4];
    const float* Wih      = (const float*)d_in[5];
    const float* Whh      = (const float*)d_in[6];
    const float* bihp     = (const float*)d_in[7];
    const float* bhhp     = (const float*)d_in[8];
    const float* mW1      = (const float*)d_in[9];
    const float* mb1      = (const float*)d_in[10];
    const float* mW2      = (const float*)d_in[11];
    const float* mb2      = (const float*)d_in[12];

    prep_kernel<<<Bn, 256>>>(band_ids, dtime);
    rnn_kernel<<<(Bn * LBn) / CPB, 256>>>(zlast, projW, projB, Wih, Whh, bihp, bhhp,
                                          mW1, mb1, mW2, mb2, (float*)d_out);
}

// round 11
// speedup vs baseline: 1.6821x; 1.0395x over previous
#include <cuda_runtime.h>

#define Bn 256
#define Tn 2048
#define Dn 64
#define LBn 2
#define DBn 32
#define Gn 96
#define Ln 2
#define CH 8      // steps per chunk
#define RD 2      // ring depth in chunks
#define CPB 4     // chains per block

__device__ float g_dts[Bn * LBn * Tn + 16];
__device__ int   g_cnt[Bn * LBn];

typedef unsigned long long u64;

__device__ __forceinline__ u64 ffma2(u64 a, u64 b, u64 c) {
    u64 d; asm("fma.rn.f32x2 %0,%1,%2,%3;" : "=l"(d) : "l"(a), "l"(b), "l"(c)); return d;
}
__device__ __forceinline__ u64 fadd2(u64 a, u64 b) {
    u64 d; asm("add.rn.f32x2 %0,%1,%2;" : "=l"(d) : "l"(a), "l"(b)); return d;
}
__device__ __forceinline__ float tanha(float x) {
    float y; asm("tanh.approx.f32 %0,%1;" : "=f"(y) : "f"(x)); return y;
}
__device__ __forceinline__ void bar_sync(int id) {
    asm volatile("bar.sync %0, 64;" :: "r"(id) : "memory");
}
__device__ __forceinline__ void bar_arrive(int id) {
    asm volatile("bar.arrive %0, 64;" :: "r"(id) : "memory");
}
__device__ __forceinline__ void membar_cta() {
    asm volatile("membar.cta;" ::: "memory");
}
__device__ __forceinline__ void cbar() { asm volatile("" ::: "memory"); }

union F2 { float2 f; u64 u; };
__device__ __forceinline__ u64 pack2(float a, float b) { F2 t; t.f = make_float2(a, b); return t.u; }
__device__ __forceinline__ float hsum(u64 a) { F2 t; t.u = a; return t.f.x + t.f.y; }

// dot of 32 floats (16 f32x2 pairs), scalar init folded into accumulator
__device__ __forceinline__ float dot32i(const u64* w, const u64* hp, float init) {
    u64 a0 = pack2(init, 0.f), a1 = 0ull, a2 = 0ull, a3 = 0ull;
#pragma unroll
    for (int k = 0; k < 16; k += 4) {
        a0 = ffma2(w[k],     hp[k],     a0);
        a1 = ffma2(w[k + 1], hp[k + 1], a1);
        a2 = ffma2(w[k + 2], hp[k + 2], a2);
        a3 = ffma2(w[k + 3], hp[k + 3], a3);
    }
    return hsum(fadd2(fadd2(a0, a1), fadd2(a2, a3)));
}
__device__ __forceinline__ void loadrow(u64* w, const float* p, float s) {
#pragma unroll
    for (int k = 0; k < 16; k++) w[k] = pack2(p[2 * k] * s, p[2 * k + 1] * s);
}
__device__ __forceinline__ void loadhp(u64* hp, const float* row) {
    const ulonglong2* hv = (const ulonglong2*)row;
#pragma unroll
    for (int k = 0; k < 8; k++) { ulonglong2 v = hv[k]; hp[2 * k] = v.x; hp[2 * k + 1] = v.y; }
}

// ---------------------------------------------------------------------------
// Prep: stable compaction of dtime per (row, band) via block prefix scan.
// ---------------------------------------------------------------------------
__global__ void prep_kernel(const int* __restrict__ band_ids,
                            const float* __restrict__ dtime) {
    const int b = blockIdx.x;
    const int tid = threadIdx.x;
    __shared__ int s_scan[256];

    int loc[8]; int cnt = 0;
    const int base = b * Tn + tid * 8;
#pragma unroll
    for (int k = 0; k < 8; k++) { loc[k] = band_ids[base + k]; cnt += loc[k]; }
    s_scan[tid] = cnt;
    __syncthreads();
    for (int off = 1; off < 256; off <<= 1) {
        int v = s_scan[tid];
        int w = (tid >= off) ? s_scan[tid - off] : 0;
        __syncthreads();
        s_scan[tid] = v + w;
        __syncthreads();
    }
    const int total = s_scan[255];
    int ones_before = s_scan[tid] - cnt;
#pragma unroll
    for (int k = 0; k < 8; k++) {
        int t = tid * 8 + k;
        int bid = loc[k];
        int pos = bid ? ones_before : (t - ones_before);
        g_dts[(b * LBn + bid) * Tn + pos] = dtime[b * Tn + t];
        ones_before += bid;
    }
    if (tid == 0) {
        g_cnt[b * LBn + 1] = total;
        g_cnt[b * LBn + 0] = Tn - total;
    }
}

// ---------------------------------------------------------------------------
// Main: 4 chains per 256-thread block (8 warps). chain = wid&3, role = wid>>2.
//   role 0: layer-1 recurrence + gx2 r,z production -> sH1 + sGX2 rings
//   role 1: layer-2 recurrence + gxn (vn @ h1 from ring) + MLP + output
// ALL weight rows in registers (5 rows of 32 per warp) — no smem weight dots.
// ---------------------------------------------------------------------------
__global__ void __launch_bounds__(256, 1)
rnn_kernel(const float* __restrict__ zlast,
           const float* __restrict__ projW, const float* __restrict__ projB,
           const float* __restrict__ Wih,   const float* __restrict__ Whh,
           const float* __restrict__ bih,   const float* __restrict__ bhh,
           const float* __restrict__ mW1,   const float* __restrict__ mb1,
           const float* __restrict__ mW2,   const float* __restrict__ mb2,
           float* __restrict__ out) {
    const int tid  = threadIdx.x;
    const int lane = tid & 31;
    const int wid  = tid >> 5;
    const int chain = wid & 3;
    const int role  = wid >> 2;

    const int cid = blockIdx.x * CPB + chain;   // == b*LBn + kb
    const int kb  = cid & 1;
    const int b   = cid >> 1;

    __shared__ __align__(16) float sH1r[CPB][RD][CH][32];   // h1 ring
    __shared__ __align__(16) float sGX2[CPB][RD][CH][64];   // gx2 r,z ring
    __shared__ __align__(16) float sH1b[CPB][32];           // W0-private h1 broadcast
    __shared__ __align__(16) float sH2b[CPB][32];           // W1-private h2 broadcast
    __shared__ float sBase[CPB][32], sW[CPB][32], sZ[CPB][64];

    if (role == 0) {
        sZ[chain][lane]      = zlast[b * Dn + lane];
        sZ[chain][lane + 32] = zlast[b * Dn + lane + 32];
        sH1b[chain][lane] = 0.f;
        sH2b[chain][lane] = 0.f;
    }
    __syncthreads();

    const int n = g_cnt[cid];
    const int nch = (n + CH - 1) / CH;
    float* outp = out + (size_t)(kb * Bn + b) * Tn;
    const float* dts = g_dts + cid * Tn;
    const int l1 = (kb * Ln + 0) * Gn;
    const int l2 = (kb * Ln + 1) * Gn;
    const int bRDY = chain * 4;       // +slot : W0 -> W1 (h1 + gx2 chunk ready)
    const int bFRE = chain * 4 + 2;   // +slot : W1 -> W0 (slot free)

    if (role == 0) {
        // ---- layer-1 recurrence + gx2 r,z production ----
        u64 wr[16], wz[16], wn[16];        // Whh layer1 (r,z half-scaled)
        loadrow(wr, &Whh[(l1 + lane) * DBn], 0.5f);
        loadrow(wz, &Whh[(l1 + lane + 32) * DBn], 0.5f);
        loadrow(wn, &Whh[(l1 + lane + 64) * DBn], 1.0f);
        u64 vr[16], vz[16];                // Wih layer2 r,z (half-scaled)
        loadrow(vr, &Wih[(l2 + lane) * DBn], 0.5f);
        loadrow(vz, &Wih[(l2 + lane + 32) * DBn], 0.5f);
        const float bhn1 = bhh[l1 + lane + 64];
        const float bir2 = 0.5f * (bih[l2 + lane] + bhh[l2 + lane]);
        const float biz2 = 0.5f * (bih[l2 + lane + 32] + bhh[l2 + lane + 32]);

        // input projection: x_t = base + dt*w
        float base = projB[kb * DBn + lane];
        float w = projW[(kb * (Dn + 1) + Dn) * DBn + lane];
#pragma unroll 8
        for (int i = 0; i < 64; i++) base += sZ[chain][i] * projW[(kb * (Dn + 1) + i) * DBn + lane];
        sBase[chain][lane] = base; sW[chain][lane] = w;
        __syncwarp();

        // collapse layer-1 input gates: gx(t) = gb + dt*gw
        float gbr, gbz, gbn, gwr, gwz, gwn;
        {
            float ar = bih[l1 + lane], cr = 0.f;
            float az = bih[l1 + lane + 32], cz = 0.f;
            float an = bih[l1 + lane + 64], cn = 0.f;
#pragma unroll 8
            for (int d = 0; d < 32; d++) {
                float wv = Wih[(l1 + lane) * DBn + d];
                ar += wv * sBase[chain][d]; cr += wv * sW[chain][d];
                wv = Wih[(l1 + lane + 32) * DBn + d];
                az += wv * sBase[chain][d]; cz += wv * sW[chain][d];
                wv = Wih[(l1 + lane + 64) * DBn + d];
                an += wv * sBase[chain][d]; cn += wv * sW[chain][d];
            }
            gbr = 0.5f * (ar + bhh[l1 + lane]);      gwr = 0.5f * cr;
            gbz = 0.5f * (az + bhh[l1 + lane + 32]); gwz = 0.5f * cz;
            gbn = an;                                 gwn = cn;
        }

        float h1s = 0.f;
        u64 hp[16];
#pragma unroll
        for (int k = 0; k < 16; k++) hp[k] = 0ull;

        float dtb[CH];
#pragma unroll
        for (int i = 0; i < CH; i++) dtb[i] = dts[i];

        for (int c = 0; c < nch; c++) {
            const int slot = c & 1;
            if (c >= RD) bar_sync(bFRE + slot);        // wait: W1 freed slot
            float dtn[CH];
#pragma unroll
            for (int i = 0; i < CH; i++) dtn[i] = dts[(c + 1) * CH + i];
#pragma unroll
            for (int i = 0; i < CH; i++) {
                const float dt = dtb[i];
                // layer-1 recurrence (critical chain)
                float sr  = dot32i(wr, hp, fmaf(dt, gwr, gbr));
                float sz  = dot32i(wz, hp, fmaf(dt, gwz, gbz));
                float ghn = dot32i(wn, hp, bhn1);
                float gxn = fmaf(dt, gwn, gbn);
                float r  = fmaf(0.5f, tanha(sr), 0.5f);
                float z  = fmaf(0.5f, tanha(sz), 0.5f);
                float nn = tanha(fmaf(r, ghn, gxn));
                h1s = fmaf(z, h1s - nn, nn);
                sH1b[chain][lane] = h1s;
                cbar();                                 // warp-synchronous STS->LDS
                loadhp(hp, sH1b[chain]);
                // publish h1 + gx2 r,z (off-chain)
                sH1r[chain][slot][i][lane] = h1s;
                sGX2[chain][slot][i][lane]      = dot32i(vr, hp, bir2);
                sGX2[chain][slot][i][lane + 32] = dot32i(vz, hp, biz2);
            }
            membar_cta();
            bar_arrive(bRDY + slot);                   // signal: chunk ready
#pragma unroll
            for (int i = 0; i < CH; i++) dtb[i] = dtn[i];
        }
    } else {
        // ---- layer-2 recurrence + gxn + MLP head + output ----
        u64 wr[16], wz[16], wn[16];        // Whh layer2 (r,z half-scaled)
        loadrow(wr, &Whh[(l2 + lane) * DBn], 0.5f);
        loadrow(wz, &Whh[(l2 + lane + 32) * DBn], 0.5f);
        loadrow(wn, &Whh[(l2 + lane + 64) * DBn], 1.0f);
        u64 vn[16];                        // Wih layer2 n-gate (full scale)
        loadrow(vn, &Wih[(l2 + lane + 64) * DBn], 1.0f);
        u64 mcol[16];                      // mW1 column `lane` (stride-32 gather)
#pragma unroll
        for (int k = 0; k < 16; k++)
            mcol[k] = pack2(mW1[kb * 1024 + (2 * k) * 32 + lane],
                            mW1[kb * 1024 + (2 * k + 1) * 32 + lane]);
        const float bhn2 = bhh[l2 + lane + 64];
        const float bin2 = bih[l2 + lane + 64];
        const float mb1v = mb1[kb * DBn + lane];
        const float mw2v = mW2[kb * DBn + lane];
        const float mb2v = mb2[kb];
        float yl = 0.f;

        float h2s = 0.f;
        u64 hp[16];
#pragma unroll
        for (int k = 0; k < 16; k++) hp[k] = 0ull;

        for (int c = 0; c < nch; c++) {
            const int slot = c & 1;
            bar_sync(bRDY + slot);                     // wait: chunk ready
#pragma unroll
            for (int i = 0; i < CH; i++) {
                const int t = c * CH + i;
                // gxn from h1 ring (off the h2 critical chain)
                u64 h1p[16];
                loadhp(h1p, sH1r[chain][slot][i]);
                float gxn = dot32i(vn, h1p, bin2);
                float gxr = sGX2[chain][slot][i][lane];
                float gxz = sGX2[chain][slot][i][lane + 32];
                // layer-2 recurrence (critical chain)
                float sr  = dot32i(wr, hp, gxr);
                float sz  = dot32i(wz, hp, gxz);
                float ghn = dot32i(wn, hp, bhn2);
                float r  = fmaf(0.5f, tanha(sr), 0.5f);
                float z  = fmaf(0.5f, tanha(sz), 0.5f);
                float nn = tanha(fmaf(r, ghn, gxn));
                h2s = fmaf(z, h2s - nn, nn);
                sH2b[chain][lane] = h2s;
                cbar();
                loadhp(hp, sH2b[chain]);
                // MLP head (off-chain ILP), mW1 column in registers
                u64 a0 = 0ull, a1 = 0ull;
#pragma unroll
                for (int k = 0; k < 16; k += 2) {
                    a0 = ffma2(mcol[k],     hp[k],     a0);
                    a1 = ffma2(mcol[k + 1], hp[k + 1], a1);
                }
                float m = fmaxf(hsum(fadd2(a0, a1)) + mb1v, 0.f);
                float y = m * mw2v;
#pragma unroll
                for (int off = 16; off > 0; off >>= 1) y += __shfl_xor_sync(0xffffffffu, y, off);
                y += mb2v;
                if (lane == 0 && t < n) outp[t] = y;
                if (t == n - 1) yl = y;
            }
            bar_arrive(bFRE + slot);                   // signal: slot free
        }
        if (n == 0) {
            float m = fmaxf(mb1v, 0.f);
            float y = m * mw2v;
#pragma unroll
            for (int off = 16; off > 0; off >>= 1) y += __shfl_xor_sync(0xffffffffu, y, off);
            yl = y + mb2v;
        }
        for (int t = n + lane; t < Tn; t += 32) outp[t] = yl;
    }
}

extern "C" void kernel_launch(void* const* d_in, const int* in_sizes, int n_in,
                              void* d_out, int out_size) {
    const int*   band_ids = (const int*)  d_in[0];
    const float* dtime    = (const float*)d_in[1];
    const float* zlast    = (const float*)d_in[2];
    const float* projW    = (const float*)d_in[3];
    const float* projB    = (const float*)d_in[4];
    const float* Wih      = (const float*)d_in[5];
    const float* Whh      = (const float*)d_in[6];
    const float* bihp     = (const float*)d_in[7];
    const float* bhhp     = (const float*)d_in[8];
    const float* mW1      = (const float*)d_in[9];
    const float* mb1      = (const float*)d_in[10];
    const float* mW2      = (const float*)d_in[11];
    const float* mb2      = (const float*)d_in[12];

    prep_kernel<<<Bn, 256>>>(band_ids, dtime);
    rnn_kernel<<<(Bn * LBn) / CPB, 256>>>(zlast, projW, projB, Wih, Whh, bihp, bhhp,
                                          mW1, mb1, mW2, mb2, (float*)d_out);
}